// round 1
// baseline (speedup 1.0000x reference)
#include <cuda_runtime.h>

#define MQ 32
#define NG 256
#define DD 128

// Block: one gallery item j, all 32 queries.
// 256 threads = 16x16 grid over (a,b); each thread owns an 8x8 tile of -Mp in regs.
__global__ __launch_bounds__(256, 2)
void jacc_pen_kernel(const float* __restrict__ qf,
                     const float* __restrict__ x,
                     const float* __restrict__ Mp,
                     const float* __restrict__ zep,
                     float* __restrict__ out) {
    const int j = blockIdx.x;
    const int t = threadIdx.x;
    const float ze = *zep;

    __shared__ float u_s[MQ][DD];          // 16 KB: u = max(qf_i, x_j), all i
    __shared__ float su_s[MQ];             // sum(max) per i
    __shared__ float sv_s[MQ];             // sum(min) per i
    __shared__ float pen_s[MQ];            // penalty accumulator per i

    const float* __restrict__ xj = x + j * DD;

    if (t < MQ) pen_s[t] = 0.0f;

    // ---- Precompute u[i][d] = max(qf[i][d], x[j][d]) for all i ----
    #pragma unroll
    for (int k = 0; k < (MQ * DD) / 256; ++k) {
        int e = t + 256 * k;
        int i = e >> 7;
        int d = e & (DD - 1);
        u_s[i][d] = fmaxf(qf[e], xj[d]);
    }

    // ---- Load this thread's 8x8 tile of Mp, negated, into registers ----
    const int ta = t >> 4;          // 0..15 -> a-block
    const int tb = t & 15;          // 0..15 -> b-block
    const int a0 = ta * 8;
    const int b0 = tb * 8;
    float nM[8][8];
    #pragma unroll
    for (int aa = 0; aa < 8; ++aa) {
        const float4* p = reinterpret_cast<const float4*>(Mp + (a0 + aa) * DD + b0);
        float4 m0 = p[0];
        float4 m1 = p[1];
        nM[aa][0] = -m0.x; nM[aa][1] = -m0.y; nM[aa][2] = -m0.z; nM[aa][3] = -m0.w;
        nM[aa][4] = -m1.x; nM[aa][5] = -m1.y; nM[aa][6] = -m1.z; nM[aa][7] = -m1.w;
    }

    // ---- Row sums for dist0: i = t/8, 8 lanes per i, 16 d's per lane ----
    {
        int i  = t >> 3;
        int d0 = (t & 7) * 16;
        float su = 0.0f, sv = 0.0f;
        #pragma unroll
        for (int d = 0; d < 16; ++d) {
            float q  = qf[i * DD + d0 + d];
            float xv = xj[d0 + d];
            su += fmaxf(q, xv);
            sv += fminf(q, xv);
        }
        #pragma unroll
        for (int off = 4; off >= 1; off >>= 1) {
            su += __shfl_down_sync(0xffffffffu, su, off, 8);
            sv += __shfl_down_sync(0xffffffffu, sv, off, 8);
        }
        if ((t & 7) == 0) { su_s[i] = su; sv_s[i] = sv; }
    }

    __syncthreads();   // u_s ready, pen_s zeroed; only barrier before the hot loop

    // ---- Hot loop: penalty for each query i ----
    #pragma unroll 1
    for (int i = 0; i < MQ; ++i) {
        float ua[8], ub[8];
        {
            float4 v0 = *reinterpret_cast<const float4*>(&u_s[i][a0]);
            float4 v1 = *reinterpret_cast<const float4*>(&u_s[i][a0 + 4]);
            ua[0] = v0.x; ua[1] = v0.y; ua[2] = v0.z; ua[3] = v0.w;
            ua[4] = v1.x; ua[5] = v1.y; ua[6] = v1.z; ua[7] = v1.w;
            float4 w0 = *reinterpret_cast<const float4*>(&u_s[i][b0]);
            float4 w1 = *reinterpret_cast<const float4*>(&u_s[i][b0 + 4]);
            ub[0] = w0.x; ub[1] = w0.y; ub[2] = w0.z; ub[3] = w0.w;
            ub[4] = w1.x; ub[5] = w1.y; ub[6] = w1.z; ub[7] = w1.w;
        }

        float acc[4] = {0.0f, 0.0f, 0.0f, 0.0f};
        #pragma unroll
        for (int aa = 0; aa < 8; ++aa) {
            #pragma unroll
            for (int bb = 0; bb < 8; ++bb) {
                float tv = fmaf(ua[aa], ub[bb], nM[aa][bb]);
                acc[bb & 3] += fmaxf(tv, ze);
            }
        }
        float w = (acc[0] + acc[1]) + (acc[2] + acc[3]);

        // warp reduce (32 lanes), then one shared atomic per warp
        #pragma unroll
        for (int off = 16; off >= 1; off >>= 1)
            w += __shfl_down_sync(0xffffffffu, w, off);
        if ((t & 31) == 0)
            atomicAdd(&pen_s[i], w);
    }

    __syncthreads();   // all penalty atomics done

    if (t < MQ) {
        out[t * NG + j] = sv_s[t] / su_s[t] - 0.001f * pen_s[t];
    }
}

extern "C" void kernel_launch(void* const* d_in, const int* in_sizes, int n_in,
                              void* d_out, int out_size) {
    const float* qf = (const float*)d_in[0];   // (32, 128)
    const float* x  = (const float*)d_in[1];   // (256, 128)
    const float* Mp = (const float*)d_in[2];   // (128, 128)
    const float* ze = (const float*)d_in[3];   // scalar
    float* out = (float*)d_out;                // (32, 256)
    (void)in_sizes; (void)n_in; (void)out_size;

    jacc_pen_kernel<<<NG, 256>>>(qf, x, Mp, ze, out);
}

// round 2
// speedup vs baseline: 1.3075x; 1.3075x over previous
#include <cuda_runtime.h>

#define MQ 32
#define NG 256
#define DD 128

__device__ __forceinline__ unsigned long long pack2(float lo, float hi) {
    unsigned long long r;
    asm("mov.b64 %0, {%1, %2};" : "=l"(r) : "f"(lo), "f"(hi));
    return r;
}
__device__ __forceinline__ unsigned long long fma2(unsigned long long a,
                                                   unsigned long long b,
                                                   unsigned long long c) {
    unsigned long long d;
    asm("fma.rn.f32x2 %0, %1, %2, %3;" : "=l"(d) : "l"(a), "l"(b), "l"(c));
    return d;
}
__device__ __forceinline__ void unpack2(unsigned long long v, float& lo, float& hi) {
    asm("mov.b64 {%0, %1}, %2;" : "=f"(lo), "=f"(hi) : "l"(v));
}

// Block = one gallery item j. 256 threads = 16x16 over (a,b); each thread owns
// an 8x8 tile of (-Mp - ze), packed as f32x2 pairs in 64 registers.
// pen(i,j) = 16384*ze + 0.5*( su_i^2 - sumMp - 16384*ze + sum|t'| ),
// t' = ua*ub - Mp - ze.  Hot loop computes only sum|t'| (FFMA2 + FADD|.|).
__global__ __launch_bounds__(256, 2)
void jacc_pen_kernel(const float* __restrict__ qf,
                     const float* __restrict__ x,
                     const float* __restrict__ Mp,
                     const float* __restrict__ zep,
                     float* __restrict__ out) {
    const int j = blockIdx.x;
    const int t = threadIdx.x;
    const float ze = *zep;

    __shared__ float u_s[MQ][DD];        // 16 KB
    __shared__ float part_s[MQ][64];     // 8 KB: per-i partial |t| sums (quad-reduced)
    __shared__ float sM_s[256];          // per-thread Mp tile sums
    __shared__ float su_s[MQ], sv_s[MQ];

    const float* __restrict__ xj = x + j * DD;

    // ---- u[i][d] = max(qf[i][d], x[j][d]) ----
    #pragma unroll
    for (int k = 0; k < (MQ * DD) / 256; ++k) {
        int e = t + 256 * k;
        int i = e >> 7;
        int d = e & (DD - 1);
        u_s[i][d] = fmaxf(qf[e], xj[d]);
    }

    // ---- dist0 row sums: i = t/8, 8 lanes per i ----
    {
        int i  = t >> 3;
        int d0 = (t & 7) * 16;
        float su = 0.0f, sv = 0.0f;
        #pragma unroll
        for (int d = 0; d < 16; ++d) {
            float q  = qf[i * DD + d0 + d];
            float xv = xj[d0 + d];
            su += fmaxf(q, xv);
            sv += fminf(q, xv);
        }
        #pragma unroll
        for (int off = 4; off >= 1; off >>= 1) {
            su += __shfl_down_sync(0xffffffffu, su, off, 8);
            sv += __shfl_down_sync(0xffffffffu, sv, off, 8);
        }
        if ((t & 7) == 0) { su_s[i] = su; sv_s[i] = sv; }
    }

    // ---- Load 8x8 Mp tile: pack (-Mp - ze) into f32x2 pairs; record tile sum ----
    const int a0 = (t >> 4) * 8;
    const int b0 = (t & 15) * 8;
    unsigned long long nM2[8][4];
    float msum = 0.0f;
    #pragma unroll
    for (int aa = 0; aa < 8; ++aa) {
        const float4* p = reinterpret_cast<const float4*>(Mp + (a0 + aa) * DD + b0);
        float4 m0 = p[0];
        float4 m1 = p[1];
        msum += ((m0.x + m0.y) + (m0.z + m0.w)) + ((m1.x + m1.y) + (m1.z + m1.w));
        nM2[aa][0] = pack2(-m0.x - ze, -m0.y - ze);
        nM2[aa][1] = pack2(-m0.z - ze, -m0.w - ze);
        nM2[aa][2] = pack2(-m1.x - ze, -m1.y - ze);
        nM2[aa][3] = pack2(-m1.z - ze, -m1.w - ze);
    }
    sM_s[t] = msum;

    __syncthreads();

    // ---- Hot loop: sum |ua*ub - Mp - ze| over the 8x8 tile, per query i ----
    #pragma unroll 1
    for (int i = 0; i < MQ; ++i) {
        float4 va0 = *reinterpret_cast<const float4*>(&u_s[i][a0]);
        float4 va1 = *reinterpret_cast<const float4*>(&u_s[i][a0 + 4]);
        float4 vb0 = *reinterpret_cast<const float4*>(&u_s[i][b0]);
        float4 vb1 = *reinterpret_cast<const float4*>(&u_s[i][b0 + 4]);
        unsigned long long ub2[4] = {
            pack2(vb0.x, vb0.y), pack2(vb0.z, vb0.w),
            pack2(vb1.x, vb1.y), pack2(vb1.z, vb1.w)
        };
        float ua[8] = {va0.x, va0.y, va0.z, va0.w, va1.x, va1.y, va1.z, va1.w};

        float acc[8] = {0,0,0,0,0,0,0,0};
        #pragma unroll
        for (int aa = 0; aa < 8; ++aa) {
            unsigned long long ua2 = pack2(ua[aa], ua[aa]);
            #pragma unroll
            for (int bp = 0; bp < 4; ++bp) {
                unsigned long long t2 = fma2(ua2, ub2[bp], nM2[aa][bp]);
                float lo, hi;
                unpack2(t2, lo, hi);
                acc[2 * bp]     += fabsf(lo);   // FADD with |src| modifier
                acc[2 * bp + 1] += fabsf(hi);
            }
        }
        float w = ((acc[0] + acc[1]) + (acc[2] + acc[3]))
                + ((acc[4] + acc[5]) + (acc[6] + acc[7]));

        // quad reduce (2 shfl), one STS per quad — no atomics, no full warp chain
        w += __shfl_down_sync(0xffffffffu, w, 2, 4);
        w += __shfl_down_sync(0xffffffffu, w, 1, 4);
        if ((t & 3) == 0) part_s[i][t >> 2] = w;
    }

    __syncthreads();

    // ---- Final phase: per-warp, finish reductions and write output ----
    {
        const int w = t >> 5;
        const int l = t & 31;

        // total sum of Mp (+ implicit ze already folded): each warp computes it
        float sm = sM_s[l];
        #pragma unroll
        for (int k = 1; k < 8; ++k) sm += sM_s[l + 32 * k];
        #pragma unroll
        for (int off = 16; off >= 1; off >>= 1)
            sm += __shfl_xor_sync(0xffffffffu, sm, off);

        #pragma unroll
        for (int ii = 0; ii < 4; ++ii) {
            int i = w * 4 + ii;
            float p = part_s[i][l] + part_s[i][l + 32];
            #pragma unroll
            for (int off = 16; off >= 1; off >>= 1)
                p += __shfl_xor_sync(0xffffffffu, p, off);
            if (l == 0) {
                float su = su_s[i];
                const float NE = (float)(DD * DD);  // 16384
                // sum t' over all (a,b) = su^2 - sumMp - NE*ze
                float pen = NE * ze + 0.5f * ((su * su - sm - NE * ze) + p);
                out[i * NG + j] = sv_s[i] / su - 0.001f * pen;
            }
        }
    }
}

extern "C" void kernel_launch(void* const* d_in, const int* in_sizes, int n_in,
                              void* d_out, int out_size) {
    const float* qf = (const float*)d_in[0];   // (32, 128)
    const float* x  = (const float*)d_in[1];   // (256, 128)
    const float* Mp = (const float*)d_in[2];   // (128, 128)
    const float* ze = (const float*)d_in[3];   // scalar
    float* out = (float*)d_out;                // (32, 256)
    (void)in_sizes; (void)n_in; (void)out_size;

    jacc_pen_kernel<<<NG, 256>>>(qf, x, Mp, ze, out);
}

// round 3
// speedup vs baseline: 1.3631x; 1.0426x over previous
#include <cuda_runtime.h>

#define MQ 32
#define NG 256
#define DD 128

__device__ __forceinline__ unsigned long long pack2(float lo, float hi) {
    unsigned long long r;
    asm("mov.b64 %0, {%1, %2};" : "=l"(r) : "f"(lo), "f"(hi));
    return r;
}
__device__ __forceinline__ unsigned long long fma2(unsigned long long a,
                                                   unsigned long long b,
                                                   unsigned long long c) {
    unsigned long long d;
    asm("fma.rn.f32x2 %0, %1, %2, %3;" : "=l"(d) : "l"(a), "l"(b), "l"(c));
    return d;
}
__device__ __forceinline__ void unpack2(unsigned long long v, float& lo, float& hi) {
    asm("mov.b64 {%0, %1}, %2;" : "=f"(lo), "=f"(hi) : "l"(v));
}

// Block = one gallery item j. 256 threads = 16x16 over (a,b); each thread owns
// an 8x8 tile of (-Mp - ze) packed as f32x2 pairs.
// pen(i,j) = 16384*ze + 0.5*( su_i^2 - sumMp - 16384*ze + sum|t'| ),
// t' = ua*ub - Mp - ze.  Hot loop computes only sum|t'|, unrolled 2 queries deep.
__global__ __launch_bounds__(256, 2)
void jacc_pen_kernel(const float* __restrict__ qf,
                     const float* __restrict__ x,
                     const float* __restrict__ Mp,
                     const float* __restrict__ zep,
                     float* __restrict__ out) {
    const int j = blockIdx.x;
    const int t = threadIdx.x;
    const float ze = *zep;

    __shared__ float u_s[MQ][DD];        // 16 KB
    __shared__ float part_s[MQ][128];    // 16 KB: per-i partials (pair-reduced)
    __shared__ float su_s[MQ], sv_s[MQ];
    __shared__ float sMw_s[8];           // per-warp Mp tile sums

    const float* __restrict__ xj = x + j * DD;

    // ---- u[i][d] = max(qf[i][d], x[j][d]) ----
    #pragma unroll
    for (int k = 0; k < (MQ * DD) / 256; ++k) {
        int e = t + 256 * k;
        int i = e >> 7;
        int d = e & (DD - 1);
        u_s[i][d] = fmaxf(qf[e], xj[d]);
    }

    // ---- dist0 row sums: i = t/8, 8 lanes per i ----
    {
        int i  = t >> 3;
        int d0 = (t & 7) * 16;
        float su = 0.0f, sv = 0.0f;
        #pragma unroll
        for (int d = 0; d < 16; ++d) {
            float q  = qf[i * DD + d0 + d];
            float xv = xj[d0 + d];
            su += fmaxf(q, xv);
            sv += fminf(q, xv);
        }
        #pragma unroll
        for (int off = 4; off >= 1; off >>= 1) {
            su += __shfl_down_sync(0xffffffffu, su, off, 8);
            sv += __shfl_down_sync(0xffffffffu, sv, off, 8);
        }
        if ((t & 7) == 0) { su_s[i] = su; sv_s[i] = sv; }
    }

    // ---- Load 8x8 Mp tile: pack (-Mp - ze) as f32x2; warp-reduce tile sum ----
    const int a0 = (t >> 4) * 8;
    const int b0 = (t & 15) * 8;
    unsigned long long nM2[8][4];
    {
        float msum = 0.0f;
        #pragma unroll
        for (int aa = 0; aa < 8; ++aa) {
            const float4* p = reinterpret_cast<const float4*>(Mp + (a0 + aa) * DD + b0);
            float4 m0 = p[0];
            float4 m1 = p[1];
            msum += ((m0.x + m0.y) + (m0.z + m0.w)) + ((m1.x + m1.y) + (m1.z + m1.w));
            nM2[aa][0] = pack2(-m0.x - ze, -m0.y - ze);
            nM2[aa][1] = pack2(-m0.z - ze, -m0.w - ze);
            nM2[aa][2] = pack2(-m1.x - ze, -m1.y - ze);
            nM2[aa][3] = pack2(-m1.z - ze, -m1.w - ze);
        }
        #pragma unroll
        for (int off = 16; off >= 1; off >>= 1)
            msum += __shfl_xor_sync(0xffffffffu, msum, off);
        if ((t & 31) == 0) sMw_s[t >> 5] = msum;
    }

    __syncthreads();

    // ---- Hot loop: sum |ua*ub - Mp - ze| over 8x8 tile, 2 queries per pass ----
    const float* urow = &u_s[0][0];
    #pragma unroll 1
    for (int i = 0; i < MQ; i += 2) {
        const float* upA = urow;
        const float* upB = urow + DD;

        float4 vA0 = *reinterpret_cast<const float4*>(upA + a0);
        float4 vA1 = *reinterpret_cast<const float4*>(upA + a0 + 4);
        float4 vB0 = *reinterpret_cast<const float4*>(upB + a0);
        float4 vB1 = *reinterpret_cast<const float4*>(upB + a0 + 4);

        const unsigned long long* bpA =
            reinterpret_cast<const unsigned long long*>(upA + b0);
        const unsigned long long* bpB =
            reinterpret_cast<const unsigned long long*>(upB + b0);
        unsigned long long ubA[4] = {bpA[0], bpA[1], bpA[2], bpA[3]};
        unsigned long long ubB[4] = {bpB[0], bpB[1], bpB[2], bpB[3]};

        float uaA[8] = {vA0.x, vA0.y, vA0.z, vA0.w, vA1.x, vA1.y, vA1.z, vA1.w};
        float uaB[8] = {vB0.x, vB0.y, vB0.z, vB0.w, vB1.x, vB1.y, vB1.z, vB1.w};

        float accA[4] = {0, 0, 0, 0};
        float accB[4] = {0, 0, 0, 0};
        #pragma unroll
        for (int aa = 0; aa < 8; ++aa) {
            unsigned long long uA2 = pack2(uaA[aa], uaA[aa]);
            unsigned long long uB2 = pack2(uaB[aa], uaB[aa]);
            #pragma unroll
            for (int bp = 0; bp < 4; ++bp) {
                float lo, hi;
                unpack2(fma2(uA2, ubA[bp], nM2[aa][bp]), lo, hi);
                accA[bp] += fabsf(lo);
                accA[(bp + 2) & 3] += fabsf(hi);
                unpack2(fma2(uB2, ubB[bp], nM2[aa][bp]), lo, hi);
                accB[bp] += fabsf(lo);
                accB[(bp + 2) & 3] += fabsf(hi);
            }
        }
        float wA = (accA[0] + accA[1]) + (accA[2] + accA[3]);
        float wB = (accB[0] + accB[1]) + (accB[2] + accB[3]);

        // one pair-shuffle, then predicated STS — short dependent tail
        wA += __shfl_down_sync(0xffffffffu, wA, 1, 2);
        wB += __shfl_down_sync(0xffffffffu, wB, 1, 2);
        if ((t & 1) == 0) {
            part_s[i][t >> 1]     = wA;
            part_s[i + 1][t >> 1] = wB;
        }

        urow += 2 * DD;
    }

    __syncthreads();

    // ---- Final phase: 8 warps x 4 queries each ----
    {
        const int w = t >> 5;
        const int l = t & 31;

        float sm = ((sMw_s[0] + sMw_s[1]) + (sMw_s[2] + sMw_s[3]))
                 + ((sMw_s[4] + sMw_s[5]) + (sMw_s[6] + sMw_s[7]));

        #pragma unroll
        for (int ii = 0; ii < 4; ++ii) {
            int i = w * 4 + ii;
            float p = (part_s[i][l]      + part_s[i][l + 32])
                    + (part_s[i][l + 64] + part_s[i][l + 96]);
            #pragma unroll
            for (int off = 16; off >= 1; off >>= 1)
                p += __shfl_xor_sync(0xffffffffu, p, off);
            if (l == 0) {
                float su = su_s[i];
                const float NE = (float)(DD * DD);  // 16384
                float pen = NE * ze + 0.5f * ((su * su - sm - NE * ze) + p);
                out[i * NG + j] = sv_s[i] / su - 0.001f * pen;
            }
        }
    }
}

extern "C" void kernel_launch(void* const* d_in, const int* in_sizes, int n_in,
                              void* d_out, int out_size) {
    const float* qf = (const float*)d_in[0];   // (32, 128)
    const float* x  = (const float*)d_in[1];   // (256, 128)
    const float* Mp = (const float*)d_in[2];   // (128, 128)
    const float* ze = (const float*)d_in[3];   // scalar
    float* out = (float*)d_out;                // (32, 256)
    (void)in_sizes; (void)n_in; (void)out_size;

    jacc_pen_kernel<<<NG, 256>>>(qf, x, Mp, ze, out);
}